// round 2
// baseline (speedup 1.0000x reference)
#include <cuda_runtime.h>
#include <cuda_fp16.h>
#include <cstdint>

// ============================================================================
// RBFEuclidean: out[b,u] = ||x_b||^2 - 2*(x@w)[b,u] + ||w_u||^2
//   x: [65536, 256] fp32, w: [256, 1024] fp32, out: [65536, 1024] fp32
//
// Build target is plain sm_103 (no 'a' suffix -> no tcgen05). Use the
// architecture-generic tensor path: mma.sync.m16n8k16 fp16 with fp32
// accumulate, ldmatrix operand loads, cp.async double-buffered tiles.
// Single-term fp16 is accurate enough (worst per-element rel err ~3e-4).
// ============================================================================

#define MB_ 65536
#define KF_ 256
#define NU_ 1024
#define BM 128
#define BN 128
#define BK 64
#define NCH (KF_ / BK)        // 4 k-chunks
#define STAGE_BYTES 32768     // A(16KB) + B(16KB)
#define SMEM_TOTAL (2 * STAGE_BYTES)

// ---- device scratch (no allocations allowed) ----
__device__ __half g_xh[(size_t)MB_ * KF_];   // x in fp16, row-major [b][k]
__device__ __half g_wh[(size_t)NU_ * KF_];   // w transposed fp16 [u][k]
__device__ float  g_xsq[MB_];
__device__ float  g_wsq[NU_];

// ---- PTX helpers (all generic sm_80+ instructions) ----
__device__ __forceinline__ uint32_t smem_to_u32(const void* p) {
    uint32_t a;
    asm("{ .reg .u64 t; cvta.to.shared.u64 t, %1; cvt.u32.u64 %0, t; }"
        : "=r"(a) : "l"(p));
    return a;
}

#define CP_ASYNC16(saddr, gptr) \
    asm volatile("cp.async.cg.shared.global [%0], [%1], 16;" \
        :: "r"(saddr), "l"(gptr) : "memory")
#define CP_COMMIT() asm volatile("cp.async.commit_group;" ::: "memory")
#define CP_WAIT1()  asm volatile("cp.async.wait_group 1;" ::: "memory")
#define CP_WAIT0()  asm volatile("cp.async.wait_group 0;" ::: "memory")

__device__ __forceinline__ void ldmatrix_x4(uint32_t& r0, uint32_t& r1,
                                            uint32_t& r2, uint32_t& r3,
                                            uint32_t addr) {
    asm volatile("ldmatrix.sync.aligned.m8n8.x4.shared.b16 {%0,%1,%2,%3}, [%4];"
        : "=r"(r0), "=r"(r1), "=r"(r2), "=r"(r3) : "r"(addr));
}

__device__ __forceinline__ void mma_16816(float* c, const uint32_t* a,
                                          const uint32_t* b) {
    asm volatile(
        "mma.sync.aligned.m16n8k16.row.col.f32.f16.f16.f32 "
        "{%0,%1,%2,%3}, {%4,%5,%6,%7}, {%8,%9}, {%0,%1,%2,%3};"
        : "+f"(c[0]), "+f"(c[1]), "+f"(c[2]), "+f"(c[3])
        : "r"(a[0]), "r"(a[1]), "r"(a[2]), "r"(a[3]), "r"(b[0]), "r"(b[1]));
}

// ============================================================================
// Pre-pass: x fp32 -> fp16 + row norms. One warp per row.
// ============================================================================
__global__ __launch_bounds__(256) void conv_x_kernel(const float* __restrict__ x) {
    int row = blockIdx.x * 8 + (threadIdx.x >> 5);
    int lane = threadIdx.x & 31;
    size_t base = (size_t)row * KF_ + lane * 8;
    float4 f0 = *(const float4*)(x + base);
    float4 f1 = *(const float4*)(x + base + 4);
    __half2 h[4];
    h[0] = __floats2half2_rn(f0.x, f0.y);
    h[1] = __floats2half2_rn(f0.z, f0.w);
    h[2] = __floats2half2_rn(f1.x, f1.y);
    h[3] = __floats2half2_rn(f1.z, f1.w);
    *(uint4*)(g_xh + base) = *(uint4*)h;
    float s = f0.x*f0.x + f0.y*f0.y + f0.z*f0.z + f0.w*f0.w
            + f1.x*f1.x + f1.y*f1.y + f1.z*f1.z + f1.w*f1.w;
#pragma unroll
    for (int o = 16; o; o >>= 1) s += __shfl_xor_sync(0xFFFFFFFFu, s, o);
    if (lane == 0) g_xsq[row] = s;
}

// Pre-pass: w fp32 [k][u] -> fp16 transposed [u][k] + col norms.
__global__ __launch_bounds__(256) void conv_w_kernel(const float* __restrict__ w) {
    int n = blockIdx.x * 256 + threadIdx.x;  // 0..1023
    float s = 0.0f;
    size_t ob = (size_t)n * KF_;
#pragma unroll 4
    for (int k = 0; k < KF_; k++) {
        float f = w[(size_t)k * NU_ + n];
        g_wh[ob + k] = __float2half_rn(f);
        s += f * f;
    }
    g_wsq[n] = s;
}

// ============================================================================
// Main GEMM + fused epilogue.
// CTA = 128x128 tile, 256 threads (8 warps as 2(m) x 4(n)), warp = 64x32.
// smem tiles k-major, 128B rows, xor-swizzled chunks for conflict-free
// ldmatrix. cp.async double buffer over 4 k-chunks of 64.
// ============================================================================
__global__ __launch_bounds__(256, 2) void rbf_gemm_kernel(float* __restrict__ out) {
    extern __shared__ char smem[];
    uint32_t sbase = smem_to_u32(smem);

    int tid = threadIdx.x;
    int wid = tid >> 5;
    int lane = tid & 31;
    int warp_m = wid & 1;    // 0..1
    int warp_n = wid >> 1;   // 0..3

    int bx = blockIdx.x;           // 4096 = 512(m) * 8(n), n fastest for A reuse
    int m0 = (bx >> 3) * BM;
    int n0 = (bx & 7) * BN;

    // ---- loader indices: thread t covers vectors v = t + i*256, v in [0,1024)
    // r = v>>3 (tile row), cc = v&7 (16B chunk); smem chunk = cc ^ (r&7)
    int lr = tid >> 3;       // base row for i=0 (rows advance by 32 per i)
    int lcc = tid & 7;

    float acc[4][4][4];
#pragma unroll
    for (int a = 0; a < 4; a++)
#pragma unroll
        for (int b = 0; b < 4; b++)
#pragma unroll
            for (int c = 0; c < 4; c++) acc[a][b][c] = 0.0f;

    // issue first stage
    {
        int k0 = 0;
        uint32_t sA = sbase;
        uint32_t sB = sbase + 16384;
#pragma unroll
        for (int i = 0; i < 4; i++) {
            int r = lr + i * 32;
            uint32_t soff = (uint32_t)(r * 128 + ((lcc ^ (r & 7)) << 4));
            CP_ASYNC16(sA + soff, g_xh + (size_t)(m0 + r) * KF_ + k0 + lcc * 8);
            CP_ASYNC16(sB + soff, g_wh + (size_t)(n0 + r) * KF_ + k0 + lcc * 8);
        }
        CP_COMMIT();
    }

    for (int c = 0; c < NCH; c++) {
        if (c + 1 < NCH) {
            int k0 = (c + 1) * BK;
            uint32_t sA = sbase + ((c + 1) & 1) * STAGE_BYTES;
            uint32_t sB = sA + 16384;
#pragma unroll
            for (int i = 0; i < 4; i++) {
                int r = lr + i * 32;
                uint32_t soff = (uint32_t)(r * 128 + ((lcc ^ (r & 7)) << 4));
                CP_ASYNC16(sA + soff, g_xh + (size_t)(m0 + r) * KF_ + k0 + lcc * 8);
                CP_ASYNC16(sB + soff, g_wh + (size_t)(n0 + r) * KF_ + k0 + lcc * 8);
            }
            CP_COMMIT();
            CP_WAIT1();
        } else {
            CP_WAIT0();
        }
        __syncthreads();

        uint32_t sA = sbase + (c & 1) * STAGE_BYTES;
        uint32_t sB = sA + 16384;

        // ldmatrix lane addressing (swizzle xor is lane&7 for all frags):
        uint32_t arow = (uint32_t)(warp_m * 64 + (lane & 15));  // + 16*mi
        uint32_t ahi = (uint32_t)(lane >> 4);                    // k-chunk half
        uint32_t brow = (uint32_t)(warp_n * 32 + ((lane >> 4) & 1) * 8 + (lane & 7)); // + 16*jj
        uint32_t bkbit = (uint32_t)((lane >> 3) & 1);
        uint32_t lxor = (uint32_t)(lane & 7);

#pragma unroll
        for (int ks = 0; ks < 4; ks++) {
            uint32_t a[4][4];
            uint32_t b[4][2];
#pragma unroll
            for (int mi = 0; mi < 4; mi++) {
                uint32_t addr = sA + (arow + 16 * mi) * 128
                              + (((2 * ks + ahi) ^ lxor) << 4);
                ldmatrix_x4(a[mi][0], a[mi][1], a[mi][2], a[mi][3], addr);
            }
#pragma unroll
            for (int jj = 0; jj < 2; jj++) {
                uint32_t r0, r1, r2, r3;
                uint32_t addr = sB + (brow + 16 * jj) * 128
                              + (((2 * ks + bkbit) ^ lxor) << 4);
                ldmatrix_x4(r0, r1, r2, r3, addr);
                b[2 * jj][0] = r0; b[2 * jj][1] = r1;
                b[2 * jj + 1][0] = r2; b[2 * jj + 1][1] = r3;
            }
#pragma unroll
            for (int mi = 0; mi < 4; mi++)
#pragma unroll
                for (int nj = 0; nj < 4; nj++)
                    mma_16816(acc[mi][nj], a[mi], b[nj]);
        }
        __syncthreads();
    }

    // ---- epilogue: out = xsq[m] + wsq[n] - 2*cross ----
    int g = lane >> 2;
    int q = lane & 3;
#pragma unroll
    for (int mi = 0; mi < 4; mi++) {
        int m_lo = m0 + warp_m * 64 + mi * 16 + g;
        float xs0 = g_xsq[m_lo];
        float xs1 = g_xsq[m_lo + 8];
        float* op0 = out + (size_t)m_lo * NU_;
        float* op1 = out + (size_t)(m_lo + 8) * NU_;
#pragma unroll
        for (int nj = 0; nj < 4; nj++) {
            int n = n0 + warp_n * 32 + nj * 8 + q * 2;
            float w0 = g_wsq[n];
            float w1 = g_wsq[n + 1];
            float2 o0, o1;
            o0.x = xs0 + w0 - 2.0f * acc[mi][nj][0];
            o0.y = xs0 + w1 - 2.0f * acc[mi][nj][1];
            o1.x = xs1 + w0 - 2.0f * acc[mi][nj][2];
            o1.y = xs1 + w1 - 2.0f * acc[mi][nj][3];
            *(float2*)(op0 + n) = o0;
            *(float2*)(op1 + n) = o1;
        }
    }
}

// ============================================================================
// Launch
// ============================================================================
extern "C" void kernel_launch(void* const* d_in, const int* in_sizes, int n_in,
                              void* d_out, int out_size) {
    const float* x = (const float*)d_in[0];
    const float* w = (const float*)d_in[1];
    float* out = (float*)d_out;

    conv_x_kernel<<<MB_ / 8, 256>>>(x);
    conv_w_kernel<<<NU_ / 256, 256>>>(w);

    cudaFuncSetAttribute(rbf_gemm_kernel,
                         cudaFuncAttributeMaxDynamicSharedMemorySize, SMEM_TOTAL);
    int grid = (MB_ / BM) * (NU_ / BN);  // 512 * 8 = 4096
    rbf_gemm_kernel<<<grid, 256, SMEM_TOTAL>>>(out);
}